// round 2
// baseline (speedup 1.0000x reference)
#include <cuda_runtime.h>
#include <math.h>

#define NCLS 100
#define O 9
#define FH 64
#define PSLOTS 584      // 72 k-sums + 4*128 histogram slots
#define HOFF1 72        // cnt1[m][v]
#define HOFF2 200       // cnt2[m][v]
#define HOFF3 328       // Sa_hist[m][v]
#define HOFF4 456       // Sb_hist[m][v]
#define K1_BLOCKS 256   // 2048 rows / 8 warps
#define K2_BLOCKS 128   // 1024 pairs / 8 warps

__device__ float g_part_pol[K2_BLOCKS * PSLOTS];
__device__ float g_part_ce[K1_BLOCKS];
__device__ float g_part_kl[K1_BLOCKS];

__device__ __forceinline__ float wredsum(float v) {
#pragma unroll
    for (int o = 16; o; o >>= 1) v += __shfl_xor_sync(0xffffffffu, v, o);
    return v;
}
__device__ __forceinline__ float wredmax(float v) {
#pragma unroll
    for (int o = 16; o; o >>= 1) v = fmaxf(v, __shfl_xor_sync(0xffffffffu, v, o));
    return v;
}

// One warp per row: CE(log_softmax) + KL(temp=4) over 100 classes.
__global__ __launch_bounds__(256) void logits_kernel(const float* __restrict__ slog,
                              const float* __restrict__ tlog,
                              const int* __restrict__ targets) {
    __shared__ float sce[8], skl[8];
    int warp = threadIdx.x >> 5, lane = threadIdx.x & 31;
    int row = blockIdx.x * 8 + warp;
    const float* s = slog + row * NCLS;
    const float* t = tlog + row * NCLS;

    float s0 = s[lane], s1 = s[lane + 32], s2 = s[lane + 64];
    float t0 = t[lane], t1 = t[lane + 32], t2 = t[lane + 64];
    bool v3 = lane < (NCLS - 96);  // lanes 0..3
    float s3 = v3 ? s[lane + 96] : -1e30f;
    float t3 = v3 ? t[lane + 96] : -1e30f;

    float ms = wredmax(fmaxf(fmaxf(s0, s1), fmaxf(s2, s3)));
    float mt = wredmax(fmaxf(fmaxf(t0, t1), fmaxf(t2, t3)));

    float es = expf(s0 - ms) + expf(s1 - ms) + expf(s2 - ms) + (v3 ? expf(s3 - ms) : 0.f);
    float lse = logf(wredsum(es));

    int lbl = targets[row * 8];
    float sel = (lane == lbl ? s0 : 0.f) + (lane + 32 == lbl ? s1 : 0.f)
              + (lane + 64 == lbl ? s2 : 0.f) + ((v3 && lane + 96 == lbl) ? s3 : 0.f);
    float slbl = wredsum(sel);
    float ce_r = -(slbl - ms - lse);

    float ms4 = 0.25f * ms, mt4 = 0.25f * mt;
    float es4 = expf(0.25f * s0 - ms4) + expf(0.25f * s1 - ms4) + expf(0.25f * s2 - ms4)
              + (v3 ? expf(0.25f * s3 - ms4) : 0.f);
    float lse4 = logf(wredsum(es4));

    float et0 = expf(0.25f * t0 - mt4), et1 = expf(0.25f * t1 - mt4);
    float et2 = expf(0.25f * t2 - mt4), et3 = v3 ? expf(0.25f * t3 - mt4) : 0.f;
    float Zt = wredsum(et0 + et1 + et2 + et3);
    float lZt = logf(Zt);

    float k0 = et0 * ((0.25f * t0 - mt4 - lZt) - (0.25f * s0 - ms4 - lse4));
    float k1 = et1 * ((0.25f * t1 - mt4 - lZt) - (0.25f * s1 - ms4 - lse4));
    float k2 = et2 * ((0.25f * t2 - mt4 - lZt) - (0.25f * s2 - ms4 - lse4));
    float k3 = v3 ? et3 * ((0.25f * t3 - mt4 - lZt) - (0.25f * s3 - ms4 - lse4)) : 0.f;
    float klr = wredsum(k0 + k1 + k2 + k3) / Zt;

    if (lane == 0) { sce[warp] = ce_r; skl[warp] = klr; }
    __syncthreads();
    if (threadIdx.x == 0) {
        float a = 0.f, b = 0.f;
#pragma unroll
        for (int i = 0; i < 8; i++) { a += sce[i]; b += skl[i]; }
        g_part_ce[blockIdx.x] = a;
        g_part_kl[blockIdx.x] = b;
    }
}

// One warp per pair p: a[p][k]=even_s·W2[k,:64], b[p][k]=odd_s·W2[k,64:],
// e/d from teacher with W1; accumulates moment sums + target-class histograms.
__global__ __launch_bounds__(256) void policy_kernel(const float* __restrict__ spol,
                              const float* __restrict__ tpol,
                              const float* __restrict__ W1,
                              const float* __restrict__ W2,
                              const int* __restrict__ targets) {
    __shared__ float sh[PSLOTS];
    int tid = threadIdx.x;
    for (int i = tid; i < PSLOTS; i += 256) sh[i] = 0.f;
    __syncthreads();

    int warp = tid >> 5, lane = tid & 31;
    int p = blockIdx.x * 8 + warp;
    const float* se = spol + (2 * p) * FH;
    const float* so = se + FH;
    const float* te = tpol + (2 * p) * FH;
    const float* to = te + FH;
    float se0 = se[lane], se1 = se[lane + 32];
    float so0 = so[lane], so1 = so[lane + 32];
    float te0 = te[lane], te1 = te[lane + 32];
    float to0 = to[lane], to1 = to[lane + 32];

    float ra[O], rb[O];
#pragma unroll
    for (int k = 0; k < O; k++) {
        const float* w2k = W2 + k * 128;
        const float* w1k = W1 + k * 128;
        float pa = se0 * w2k[lane] + se1 * w2k[lane + 32];
        float pb = so0 * w2k[lane + 64] + so1 * w2k[lane + 96];
        float pe = te0 * w1k[lane] + te1 * w1k[lane + 32];
        float pd = to0 * w1k[lane + 64] + to1 * w1k[lane + 96];
#pragma unroll
        for (int off = 16; off; off >>= 1) {
            pa += __shfl_xor_sync(0xffffffffu, pa, off);
            pb += __shfl_xor_sync(0xffffffffu, pb, off);
            pe += __shfl_xor_sync(0xffffffffu, pe, off);
            pd += __shfl_xor_sync(0xffffffffu, pd, off);
        }
        ra[k] = pa; rb[k] = pb;
        float dv = 0.f;
        switch (lane) {
            case 0: dv = pa; break;
            case 1: dv = pb; break;
            case 2: dv = pe; break;
            case 3: dv = pd; break;
            case 4: dv = (pa - pe) * (pa - pe); break;  // Σ(a−e)²
            case 5: dv = (pb - pd) * (pb - pd); break;  // Σ(b−d)²
            case 6: dv = pa * pa; break;
            case 7: dv = pb * pb; break;
            default: break;
        }
        if (lane < 8) atomicAdd(&sh[k * 8 + lane], dv);
    }

    if (lane == 0) {
#pragma unroll
        for (int m = 0; m < 8; m++) {
            int v1 = targets[(2 * p) * 8 + m];     v1 = v1 < 0 ? 0 : (v1 > 15 ? 15 : v1);
            int v2 = targets[(2 * p + 1) * 8 + m]; v2 = v2 < 0 ? 0 : (v2 > 15 ? 15 : v2);
            atomicAdd(&sh[HOFF1 + m * 16 + v1], 1.f);
            atomicAdd(&sh[HOFF3 + m * 16 + v1], ra[m + 1]);
            atomicAdd(&sh[HOFF2 + m * 16 + v2], 1.f);
            atomicAdd(&sh[HOFF4 + m * 16 + v2], rb[m + 1]);
        }
    }
    __syncthreads();
    for (int i = tid; i < PSLOTS; i += 256) g_part_pol[blockIdx.x * PSLOTS + i] = sh[i];
}

// Single block (256 threads): reduce partials, evaluate closed form in double.
__global__ __launch_bounds__(256) void final_kernel(const float* __restrict__ bias1,
                             const float* __restrict__ bias2,
                             float* __restrict__ out) {
    __shared__ float red[PSLOTS];
    __shared__ float s_ce, s_kl;
    int tid = threadIdx.x;
    for (int slot = tid; slot < PSLOTS; slot += 256) {
        float acc = 0.f;
        for (int b = 0; b < K2_BLOCKS; b++) acc += g_part_pol[b * PSLOTS + slot];
        red[slot] = acc;
    }
    int warp = tid >> 5, lane = tid & 31;
    if (warp == 0) {
        float a = 0.f;
        for (int i = lane; i < K1_BLOCKS; i += 32) a += g_part_ce[i];
        a = wredsum(a);
        if (lane == 0) s_ce = a;
    }
    if (warp == 1) {
        float a = 0.f;
        for (int i = lane; i < K1_BLOCKS; i += 32) a += g_part_kl[i];
        a = wredsum(a);
        if (lane == 0) s_kl = a;
    }
    __syncthreads();
    if (tid == 0) {
        const double n = 1024.0, n2 = n * n;
        double c[O], f[O];
        for (int k = 0; k < O; k++) { c[k] = bias2[k]; f[k] = bias1[k]; }

        double Sa[O], Sb[O], Saa[O], Sbb[O];
        double klpol = 0.0, accP = 0.0;
        for (int k = 0; k < O; k++) {
            double sa = red[k * 8 + 0], sb = red[k * 8 + 1];
            double sE = red[k * 8 + 2], sd = red[k * 8 + 3];
            double syy = red[k * 8 + 4], sxx = red[k * 8 + 5];
            double saa = red[k * 8 + 6], sbb = red[k * 8 + 7];
            Sa[k] = sa; Sb[k] = sb; Saa[k] = saa; Sbb[k] = sbb;
            double dx = sb - sd, dy = sa - sE, dl = c[k] - f[k];
            // Σ_{i,j}((b−d)_i+(a−e)_j+δ)²
            double ss = n * sxx + n * syy + n2 * dl * dl + 2.0 * dx * dy + 2.0 * n * dl * (dx + dy);
            if (k == 0)      klpol += ss / n2;          // POS_W[0]=NEG_W[0]=1.0
            else if (k == 1) klpol += 0.5 * ss / n2;    // 0.5
            else             accP += ss;                // 0.001, /(7 n²)
        }
        klpol += 0.001 * accP / (7.0 * n2);

        // kldiv(sI,gI): gI diag == 1.0 exactly → −Σ_i sI[i,i]/n²
        double term1 = -(Sa[0] + Sb[0] + n * c[0]) / n2;

        double eqs[8];
        for (int m = 0; m < 8; m++) {
            double e = 0.0;
            for (int v = 0; v < 16; v++) {
                double c1 = red[HOFF1 + m * 16 + v], c2 = red[HOFF2 + m * 16 + v];
                double sav = red[HOFF3 + m * 16 + v], sbv = red[HOFF4 + m * 16 + v];
                e += c1 * sbv + c2 * sav + c1 * c2 * c[m + 1];
            }
            eqs[m] = e;
        }
        // kldiv(sC,gC): only eq pairs (gC=1, log 1 = 0) → −Σ_eq sC; weight mean = 0.5
        double term2 = -0.5 * eqs[0] / n2;

        // 0.001 * mean over 7n² of (sP − gP)², gP=±1
        double t3 = 0.0;
        for (int k = 2; k < O; k++) {
            int m = k - 1;
            double sumsq_s = n * Sbb[k] + n * Saa[k] + n2 * c[k] * c[k]
                           + 2.0 * Sa[k] * Sb[k] + 2.0 * n * c[k] * (Sa[k] + Sb[k]);
            double sum_s = n * (Sa[k] + Sb[k]) + n2 * c[k];
            double ssg = 2.0 * eqs[m] - sum_s;  // Σ s·g with g=2·eq−1
            t3 += sumsq_s - 2.0 * ssg + n2;
        }
        double term3 = 0.001 * t3 / (7.0 * n2);

        double pol = klpol + term1 + term2 + term3;
        double ce = (double)s_ce / 2048.0;
        double kl = (double)s_kl * 16.0 / (2048.0 * 100.0);
        out[0] = (float)(ce + kl + pol);
    }
}

extern "C" void kernel_launch(void* const* d_in, const int* in_sizes, int n_in,
                              void* d_out, int out_size) {
    const float* slog = (const float*)d_in[0];
    const float* tlog = (const float*)d_in[1];
    const float* spol = (const float*)d_in[2];
    const float* tpol = (const float*)d_in[3];
    const float* W1   = (const float*)d_in[4];
    const float* b1   = (const float*)d_in[5];
    const float* W2   = (const float*)d_in[6];
    const float* b2   = (const float*)d_in[7];
    const int* targets = (const int*)d_in[8];

    logits_kernel<<<K1_BLOCKS, 256>>>(slog, tlog, targets);
    policy_kernel<<<K2_BLOCKS, 256>>>(spol, tpol, W1, W2, targets);
    final_kernel<<<1, 256>>>(b1, b2, (float*)d_out);
}

// round 3
// speedup vs baseline: 3.1780x; 3.1780x over previous
#include <cuda_runtime.h>
#include <math.h>

#define NCLS 100
#define O 9
#define FH 64
#define K1_BLOCKS 256   // 2048 rows / 8 warps
#define K2_BLOCKS 32    // 1024 pairs / (8 warps * 4 pairs)
#define PPW 4           // pairs per warp
#define PSLOTS 88       // 72 moment sums + 8 e1 + 8 e2

// counts: [0..127] cnt1[m][v] (even rows), [128..255] cnt2[m][v] (odd rows)
__device__ int   g_cnt[256];
__device__ float g_part_pol[PSLOTS * K2_BLOCKS];   // slot-major
__device__ float g_part_ce[K1_BLOCKS];
__device__ float g_part_kl[K1_BLOCKS];

__device__ __forceinline__ float wredsum(float v) {
#pragma unroll
    for (int o = 16; o; o >>= 1) v += __shfl_xor_sync(0xffffffffu, v, o);
    return v;
}
__device__ __forceinline__ double dredsum(double v) {
#pragma unroll
    for (int o = 16; o; o >>= 1) v += __shfl_xor_sync(0xffffffffu, v, o);
    return v;
}

// One warp per row: CE + temp-4 KL over 100 classes; also target-count histogram.
__global__ __launch_bounds__(256) void logits_kernel(const float* __restrict__ slog,
                              const float* __restrict__ tlog,
                              const int* __restrict__ targets) {
    __shared__ float sce[8], skl[8];
    int warp = threadIdx.x >> 5, lane = threadIdx.x & 31;
    int row = blockIdx.x * 8 + warp;
    const float* s = slog + row * NCLS;
    const float* t = tlog + row * NCLS;

    // global integer count histogram (deterministic int atomics)
    if (lane < 8) {
        int v = targets[row * 8 + lane];
        v = v < 0 ? 0 : (v > 15 ? 15 : v);
        atomicAdd(&g_cnt[(row & 1) * 128 + lane * 16 + v], 1);
    }

    float s0 = s[lane], s1 = s[lane + 32], s2 = s[lane + 64];
    float t0 = t[lane], t1 = t[lane + 32], t2 = t[lane + 64];
    bool v3 = lane < (NCLS - 96);  // lanes 0..3
    float s3 = v3 ? s[lane + 96] : -1e30f;
    float t3 = v3 ? t[lane + 96] : -1e30f;

    // combined max reduce (2 chains, ILP)
    float ms = fmaxf(fmaxf(s0, s1), fmaxf(s2, s3));
    float mt = fmaxf(fmaxf(t0, t1), fmaxf(t2, t3));
#pragma unroll
    for (int o = 16; o; o >>= 1) {
        ms = fmaxf(ms, __shfl_xor_sync(0xffffffffu, ms, o));
        mt = fmaxf(mt, __shfl_xor_sync(0xffffffffu, mt, o));
    }
    float ms4 = 0.25f * ms, mt4 = 0.25f * mt;

    // full-temp softmax sum for CE
    float es = __expf(s0 - ms) + __expf(s1 - ms) + __expf(s2 - ms)
             + (v3 ? __expf(s3 - ms) : 0.f);

    // temp-4 terms
    float x0 = 0.25f * s0 - ms4, x1 = 0.25f * s1 - ms4, x2 = 0.25f * s2 - ms4, x3 = 0.25f * s3 - ms4;
    float y0 = 0.25f * t0 - mt4, y1 = 0.25f * t1 - mt4, y2 = 0.25f * t2 - mt4, y3 = 0.25f * t3 - mt4;
    float es4 = __expf(x0) + __expf(x1) + __expf(x2) + (v3 ? __expf(x3) : 0.f);
    float e0 = __expf(y0), e1 = __expf(y1), e2 = __expf(y2), e3 = v3 ? __expf(y3) : 0.f;
    float Zt  = e0 + e1 + e2 + e3;
    float sum1 = e0 * (y0 - x0) + e1 * (y1 - x1) + e2 * (y2 - x2) + e3 * (y3 - x3);

    // combined sum reduce (4 chains, ILP)
#pragma unroll
    for (int o = 16; o; o >>= 1) {
        es   += __shfl_xor_sync(0xffffffffu, es,   o);
        es4  += __shfl_xor_sync(0xffffffffu, es4,  o);
        Zt   += __shfl_xor_sync(0xffffffffu, Zt,   o);
        sum1 += __shfl_xor_sync(0xffffffffu, sum1, o);
    }
    float lse = __logf(es), lse4 = __logf(es4), lZt = __logf(Zt);

    int lbl = targets[row * 8];                  // label in [0,10) < 32
    float slbl = __shfl_sync(0xffffffffu, s0, lbl);
    float ce_r = ms + lse - slbl;
    float klr  = sum1 / Zt - lZt + lse4;

    if (lane == 0) { sce[warp] = ce_r; skl[warp] = klr; }
    __syncthreads();
    if (threadIdx.x == 0) {
        float a = 0.f, b = 0.f;
#pragma unroll
        for (int i = 0; i < 8; i++) { a += sce[i]; b += skl[i]; }
        g_part_ce[blockIdx.x] = a;
        g_part_kl[blockIdx.x] = b;
    }
}

// One warp per 4 pairs: dot products via butterfly reduce; moment sums + eq-dot
// terms accumulated in registers across pairs, then shared, then 88 slot-major floats.
__global__ __launch_bounds__(256) void policy_kernel(const float* __restrict__ spol,
                              const float* __restrict__ tpol,
                              const float* __restrict__ W1,
                              const float* __restrict__ W2,
                              const int* __restrict__ targets) {
    __shared__ float w1s[O * 128], w2s[O * 128];
    __shared__ int cnts[256];
    __shared__ float acc[PSLOTS];
    int tid = threadIdx.x;
    for (int i = tid; i < O * 128; i += 256) { w1s[i] = W1[i]; w2s[i] = W2[i]; }
    if (tid < 256) cnts[tid] = g_cnt[tid];
    if (tid < PSLOTS) acc[tid] = 0.f;
    __syncthreads();

    int warp = tid >> 5, lane = tid & 31;
    int p0 = (blockIdx.x * 8 + warp) * PPW;

    float mom[O];
#pragma unroll
    for (int k = 0; k < O; k++) mom[k] = 0.f;
    float e1acc = 0.f, e2acc = 0.f;

#pragma unroll
    for (int pi = 0; pi < PPW; pi++) {
        int p = p0 + pi;
        const float* se = spol + (2 * p) * FH;
        const float* so = se + FH;
        const float* te = tpol + (2 * p) * FH;
        const float* to = te + FH;
        float se0 = se[lane], se1 = se[lane + 32];
        float so0 = so[lane], so1 = so[lane + 32];
        float te0 = te[lane], te1 = te[lane + 32];
        float to0 = to[lane], to1 = to[lane + 32];

        // per-m target values for this pair (lane m holds its own)
        int v1 = 0, v2 = 0;
        if (lane < 8) {
            v1 = targets[16 * p + lane];     v1 = v1 < 0 ? 0 : (v1 > 15 ? 15 : v1);
            v2 = targets[16 * p + 8 + lane]; v2 = v2 < 0 ? 0 : (v2 > 15 ? 15 : v2);
        }

        float myra = 0.f, myrb = 0.f;
#pragma unroll
        for (int k = 0; k < O; k++) {
            const float* w2k = w2s + k * 128;
            const float* w1k = w1s + k * 128;
            float pa = se0 * w2k[lane] + se1 * w2k[lane + 32];
            float pb = so0 * w2k[lane + 64] + so1 * w2k[lane + 96];
            float pe = te0 * w1k[lane] + te1 * w1k[lane + 32];
            float pd = to0 * w1k[lane + 64] + to1 * w1k[lane + 96];
#pragma unroll
            for (int off = 16; off; off >>= 1) {
                pa += __shfl_xor_sync(0xffffffffu, pa, off);
                pb += __shfl_xor_sync(0xffffffffu, pb, off);
                pe += __shfl_xor_sync(0xffffffffu, pe, off);
                pd += __shfl_xor_sync(0xffffffffu, pd, off);
            }
            // lane l<8 accumulates moment type l for this k (values are broadcast)
            float dv;
            switch (lane) {
                case 0: dv = pa; break;
                case 1: dv = pb; break;
                case 2: dv = pe; break;
                case 3: dv = pd; break;
                case 4: dv = (pa - pe) * (pa - pe); break;  // Σ_j (a−e)²
                case 5: dv = (pb - pd) * (pb - pd); break;  // Σ_i (b−d)²
                case 6: dv = pa * pa; break;
                case 7: dv = pb * pb; break;
                default: dv = 0.f; break;
            }
            mom[k] += dv;
            if (lane == k - 1) { myra = pa; myrb = pb; }  // lane m keeps k=m+1
        }
        if (lane < 8) {
            e1acc += myra * (float)cnts[128 + lane * 16 + v1];  // Σ_j a·cnt2[v1_j]
            e2acc += myrb * (float)cnts[lane * 16 + v2];        // Σ_i b·cnt1[v2_i]
        }
    }

    if (lane < 8) {
#pragma unroll
        for (int k = 0; k < O; k++) atomicAdd(&acc[k * 8 + lane], mom[k]);
        atomicAdd(&acc[72 + lane], e1acc);
        atomicAdd(&acc[80 + lane], e2acc);
    }
    __syncthreads();
    if (tid < PSLOTS) g_part_pol[tid * K2_BLOCKS + blockIdx.x] = acc[tid];
}

// Single block: vectorized slot reduce + lane-parallel fp64 closed form.
__global__ __launch_bounds__(256) void final_kernel(const float* __restrict__ bias1,
                             const float* __restrict__ bias2,
                             float* __restrict__ out) {
    __shared__ float red[PSLOTS];
    __shared__ float ccs[8];
    __shared__ float s_ce, s_kl;
    int tid = threadIdx.x, warp = tid >> 5, lane = tid & 31;

    if (tid < PSLOTS) {
        const float4* v = (const float4*)(g_part_pol + tid * K2_BLOCKS);
        float4 a0 = v[0], a1 = v[1], a2 = v[2], a3 = v[3];
        float4 a4 = v[4], a5 = v[5], a6 = v[6], a7 = v[7];
        float s = ((a0.x + a0.y) + (a0.z + a0.w)) + ((a1.x + a1.y) + (a1.z + a1.w))
                + ((a2.x + a2.y) + (a2.z + a2.w)) + ((a3.x + a3.y) + (a3.z + a3.w))
                + ((a4.x + a4.y) + (a4.z + a4.w)) + ((a5.x + a5.y) + (a5.z + a5.w))
                + ((a6.x + a6.y) + (a6.z + a6.w)) + ((a7.x + a7.y) + (a7.z + a7.w));
        red[tid] = s;
    }
    if (warp == 4) {
        float a = 0.f;
        for (int i = lane; i < K1_BLOCKS; i += 32) a += g_part_ce[i];
        a = wredsum(a);
        if (lane == 0) s_ce = a;
    }
    if (warp == 5) {
        float a = 0.f;
        for (int i = lane; i < K1_BLOCKS; i += 32) a += g_part_kl[i];
        a = wredsum(a);
        if (lane == 0) s_kl = a;
    }
    if (warp == 6 && lane < 8) {
        int cc = 0;
#pragma unroll
        for (int v = 0; v < 16; v++) cc += g_cnt[lane * 16 + v] * g_cnt[128 + lane * 16 + v];
        ccs[lane] = (float)cc;
    }
    __syncthreads();

    if (warp == 0) {
        const double n = 1024.0, n2 = n * n;
        double P = 0.0;
        int k = lane;
        if (k < O) {
            double sa = red[k * 8 + 0], sb = red[k * 8 + 1];
            double sE = red[k * 8 + 2], sd = red[k * 8 + 3];
            double syy = red[k * 8 + 4], sxx = red[k * 8 + 5];
            double saa = red[k * 8 + 6], sbb = red[k * 8 + 7];
            double c = bias2[k], f = bias1[k];
            double dx = sb - sd, dy = sa - sE, dl = c - f;
            double ss = n * sxx + n * syy + n2 * dl * dl + 2.0 * dx * dy + 2.0 * n * dl * (dx + dy);
            double w = (k == 0) ? 1.0 : (k == 1) ? 0.5 : (0.001 / 7.0);
            P = w * ss / n2;
            if (k == 0) {
                P += -(sa + sb + n * c) / n2;                 // kldiv(sI,gI)
            } else {
                int m = k - 1;
                double eq = (double)red[72 + m] + (double)red[80 + m] + c * (double)ccs[m];
                if (k == 1) {
                    P += -0.5 * eq / n2;                      // kldiv(sC,gC)·mean-w
                } else {
                    double sumsq_s = n * sbb + n * saa + n2 * c * c
                                   + 2.0 * sa * sb + 2.0 * n * c * (sa + sb);
                    double sum_s = n * (sa + sb) + n2 * c;
                    double ssg = 2.0 * eq - sum_s;            // Σ s·g, g = 2·eq−1
                    P += 0.001 * (sumsq_s - 2.0 * ssg + n2) / (7.0 * n2);
                }
            }
        }
        double pol = dredsum(P);
        if (lane == 0) {
            double ce = (double)s_ce / 2048.0;
            double kl = (double)s_kl * 16.0 / (2048.0 * 100.0);
            out[0] = (float)(ce + kl + pol);
        }
    }
}

extern "C" void kernel_launch(void* const* d_in, const int* in_sizes, int n_in,
                              void* d_out, int out_size) {
    const float* slog = (const float*)d_in[0];
    const float* tlog = (const float*)d_in[1];
    const float* spol = (const float*)d_in[2];
    const float* tpol = (const float*)d_in[3];
    const float* W1   = (const float*)d_in[4];
    const float* b1   = (const float*)d_in[5];
    const float* W2   = (const float*)d_in[6];
    const float* b2   = (const float*)d_in[7];
    const int* targets = (const int*)d_in[8];

    void* cnt_ptr = nullptr;
    cudaGetSymbolAddress(&cnt_ptr, g_cnt);
    cudaMemsetAsync(cnt_ptr, 0, 256 * sizeof(int));

    logits_kernel<<<K1_BLOCKS, 256>>>(slog, tlog, targets);
    policy_kernel<<<K2_BLOCKS, 256>>>(spol, tpol, W1, W2, targets);
    final_kernel<<<1, 256>>>(b1, b2, (float*)d_out);
}